// round 14
// baseline (speedup 1.0000x reference)
#include <cuda_runtime.h>
#include <cuda_fp16.h>
#include <math.h>
#include <stdint.h>

#define BB  8
#define TT  2048
#define CH  1024

#define NTC   (BB * TT * CH)              // 16,777,216
#define NTT   ((size_t)BB * TT * TT)      // 33,554,432

// ---------------- scratch (no allocations allowed) ----------------
__device__ __half g_hQ [NTC];
__device__ __half g_hK [NTC];
__device__ __half g_hKT[NTC];             // per-batch [CH][TT]
__device__ __half g_hUT [CH * CH];
__device__ __half g_hW1T[CH * CH];
__device__ __half g_hW2T[CH * CH];
__device__ __half g_f1h[NTC];
__device__ __half g_f2h[NTC];
__device__ __half g_hS [NTT];             // f16 exp(scores)
__device__ float  g_part[BB * TT * 16];
__device__ float  g_invs[BB * TT];
__device__ float  g_ctx[NTC];
__device__ __half g_hLN[NTC];
__device__ __half g_hH [NTC];

enum { EPI_PROJ = 0, EPI_EXP, EPI_CTX, EPI_BIAS_RELU, EPI_BIAS };

// ---------------- PTX helpers ----------------
__device__ __forceinline__ uint32_t smem_u32(const void* p) {
    uint32_t a;
    asm("{ .reg .u64 t; cvta.to.shared.u64 t, %1; cvt.u32.u64 %0, t; }" : "=r"(a) : "l"(p));
    return a;
}
__device__ __forceinline__ void ldsm4(uint32_t* r, uint32_t addr) {
    asm volatile("ldmatrix.sync.aligned.m8n8.x4.shared.b16 {%0,%1,%2,%3}, [%4];"
        : "=r"(r[0]), "=r"(r[1]), "=r"(r[2]), "=r"(r[3]) : "r"(addr));
}
__device__ __forceinline__ void mma_f16(float* d, const uint32_t* a, const uint32_t* b) {
    asm volatile(
        "mma.sync.aligned.m16n8k16.row.col.f32.f16.f16.f32 "
        "{%0,%1,%2,%3}, {%4,%5,%6,%7}, {%8,%9}, {%0,%1,%2,%3};"
        : "+f"(d[0]), "+f"(d[1]), "+f"(d[2]), "+f"(d[3])
        : "r"(a[0]), "r"(a[1]), "r"(a[2]), "r"(a[3]), "r"(b[0]), "r"(b[1]));
}
#define CP16(dst, src) \
    asm volatile("cp.async.cg.shared.global [%0], [%1], 16;" :: "r"(dst), "l"(src) : "memory")
#define CP_COMMIT()  asm volatile("cp.async.commit_group;" ::: "memory")
#define CP_WAIT1()   asm volatile("cp.async.wait_group 1;" ::: "memory")
#define CP_WAIT0()   asm volatile("cp.async.wait_group 0;" ::: "memory")

// swizzled offset within a k32 subtile: rows of 64B (32 halves), 16B column c (0..3)
__device__ __forceinline__ uint32_t swz(int row, int c) {
    return (uint32_t)(row * 64 + (((c) ^ ((row >> 1) & 3)) << 4));
}

// CTA tile 128x128, STAGE = K64 (two k32 subtiles), 3-stage cp.async ring,
// 8 warps (4m x 2n) of 32x64, 256 threads, 2 CTAs/SM.
#define BM 128
#define BN 128
#define A_BYTES (BM * 64)                 // 8192 per subtile
#define B_BYTES (BN * 64)                 // 8192 per subtile
#define SUBSTG  (A_BYTES + B_BYTES)       // 16384
#define STAGE   (2 * SUBSTG)              // 32768 (K=64)
#define SMEM_G  (3 * STAGE)               // 98304
#define NTHR    256

#define GEMM_SETUP()                                                           \
    extern __shared__ char smem[];                                             \
    const uint32_t sb = smem_u32(smem);                                        \
    const int tid = threadIdx.x, lane = tid & 31, warp = tid >> 5;             \
    const int wm = warp >> 1, wn = warp & 1;                                   \
    const int z = blockIdx.z;                                                  \
    uint32_t adst[2], bdst[2];                                                 \
    const __half* asrc[2];                                                     \
    const __half* bsrc[2];                                                     \
    _Pragma("unroll")                                                          \
    for (int i = 0; i < 2; i++) {                                              \
        int q = tid + i * NTHR, r = q >> 2, c = q & 3;                         \
        adst[i] = swz(r, c);                                                   \
        asrc[i] = Ap + (long)r * K + c * 8;                                    \
        bdst[i] = A_BYTES + swz(r, c);                                         \
        bsrc[i] = Bp + (long)r * K + c * 8;                                    \
    }                                                                          \
    const int q8 = lane >> 3, rr = lane & 7;                                   \
    const int rA = wm * 32 + (q8 & 1) * 8 + rr;                                \
    const int xA = (rA >> 1) & 3;                                              \
    const int cA = q8 >> 1;                                                    \
    const int rB = wn * 64 + (q8 >> 1) * 8 + rr;                               \
    const int xB = (rB >> 1) & 3;                                              \
    const int cB = q8 & 1;

// one stage = K64: two k32 subtiles, single commit
#define ISSUE(st)                                                              \
    do {                                                                       \
        const uint32_t _s = sb + ((st) % 3) * STAGE;                           \
        _Pragma("unroll")                                                      \
        for (int _sub = 0; _sub < 2; _sub++) {                                 \
            const long _ko = (long)(st) * 64 + _sub * 32;                      \
            const uint32_t _d = _s + _sub * SUBSTG;                            \
            CP16(_d + adst[0], asrc[0] + _ko);                                 \
            CP16(_d + adst[1], asrc[1] + _ko);                                 \
            CP16(_d + bdst[0], bsrc[0] + _ko);                                 \
            CP16(_d + bdst[1], bsrc[1] + _ko);                                 \
        }                                                                      \
        CP_COMMIT();                                                           \
    } while (0)

// Early-issue mainloop: prefetch for stage kt+2 is launched IMMEDIATELY after
// the barrier (buffer (kt+2)%3 was fully consumed before this barrier), so the
// DRAM latency countdown overlaps the whole compute block instead of trailing it.
#define MAINLOOP()                                                             \
    ISSUE(0);                                                                  \
    ISSUE(1);                                                                  \
    const int nSt = K / 64;                                                    \
    for (int st = 0; st < nSt; st++) {                                         \
        if (st + 1 < nSt) CP_WAIT1(); else CP_WAIT0();                         \
        __syncthreads();                                                       \
        if (st + 2 < nSt) ISSUE(st + 2);                                       \
        const uint32_t stbase = sb + (st % 3) * STAGE;                         \
        _Pragma("unroll")                                                      \
        for (int sub = 0; sub < 2; sub++) {                                    \
            const uint32_t sbase = stbase + sub * SUBSTG;                      \
            _Pragma("unroll")                                                  \
            for (int s = 0; s < 2; s++) {                                      \
                uint32_t af[2][4];                                             \
                _Pragma("unroll")                                              \
                for (int mi = 0; mi < 2; mi++)                                 \
                    ldsm4(af[mi], sbase + (uint32_t)((rA + mi * 16) * 64) +    \
                                  (uint32_t)((((2 * s + cA) ^ xA)) << 4));     \
                _Pragma("unroll")                                              \
                for (int nip = 0; nip < 4; nip++) {                            \
                    uint32_t t4[4];                                            \
                    ldsm4(t4, sbase + A_BYTES + (uint32_t)((rB + nip * 16) * 64) + \
                              (uint32_t)((((2 * s + cB) ^ xB)) << 4));         \
                    _Pragma("unroll")                                          \
                    for (int mi = 0; mi < 2; mi++) mma_f16(acc[mi][2 * nip],     af[mi], &t4[0]); \
                    _Pragma("unroll")                                          \
                    for (int mi = 0; mi < 2; mi++) mma_f16(acc[mi][2 * nip + 1], af[mi], &t4[2]); \
                }                                                              \
            }                                                                  \
        }                                                                      \
    }

// ---------------- f16-in / f32-acc GEMM, fused epilogues ----------------
template <int EPI, bool OUTH>
__global__ void __launch_bounds__(NTHR, 2)
gemmvA(const __half* __restrict__ A, const __half* __restrict__ A2,
       const __half* __restrict__ B, void* __restrict__ Cv, void* __restrict__ Cv2,
       int M, int N, int K, long sA, long sB, long sC,
       const float* __restrict__ vec, long sVec,
       const float* __restrict__ add, long sAdd, float scale,
       float* __restrict__ part)
{
    const __half* Abase = A;
    void* Cbase = Cv;
    if (EPI == EPI_PROJ && blockIdx.z == 1) { Abase = A2; Cbase = Cv2; }
    const __half* Ap = Abase + (long)blockIdx.z * sA + (long)(blockIdx.y * BM) * K;
    const __half* Bp = B + (long)blockIdx.z * sB + (long)(blockIdx.x * BN) * K;

    GEMM_SETUP();

    float acc[2][8][4];
#pragma unroll
    for (int mi = 0; mi < 2; mi++)
#pragma unroll
        for (int ni = 0; ni < 8; ni++)
#pragma unroll
            for (int e = 0; e < 4; e++) acc[mi][ni][e] = 0.f;

    MAINLOOP();

    const float* vv = vec ? vec + (long)z * sVec : nullptr;
    const long cBase = (long)z * sC;

    if (EPI == EPI_EXP) {
        float rsl[2][2] = {{0.f, 0.f}, {0.f, 0.f}};
#pragma unroll
        for (int mi = 0; mi < 2; mi++) {
            const int r0 = blockIdx.y * BM + wm * 32 + mi * 16 + (lane >> 2);
#pragma unroll
            for (int ni = 0; ni < 8; ni++) {
                const int c = blockIdx.x * BN + wn * 64 + ni * 8 + (lane & 3) * 2;
                const float m0 = vv[c], m1 = vv[c + 1];
#pragma unroll
                for (int p = 0; p < 2; p++) {
                    const int r = r0 + p * 8;
                    float e0 = (m0 == 0.f) ? 0.f : expf(acc[mi][ni][p * 2 + 0] * scale);
                    float e1 = (m1 == 0.f) ? 0.f : expf(acc[mi][ni][p * 2 + 1] * scale);
                    __half2 h = __floats2half2_rn(e0, e1);
                    *(__half2*)((__half*)Cv + cBase + (long)r * N + c) = h;
                    float2 fr = __half22float2(h);
                    rsl[mi][p] += fr.x + fr.y;
                }
            }
        }
        float* rsf = (float*)(smem + (nSt % 3) * STAGE);
#pragma unroll
        for (int mi = 0; mi < 2; mi++)
#pragma unroll
            for (int p = 0; p < 2; p++) {
                float s = rsl[mi][p];
                s += __shfl_xor_sync(0xffffffffu, s, 1);
                s += __shfl_xor_sync(0xffffffffu, s, 2);
                if ((lane & 3) == 0)
                    rsf[(wm * 32 + mi * 16 + p * 8 + (lane >> 2)) * 2 + wn] = s;
            }
        __syncthreads();
        if (tid < BM) {
            float s = rsf[tid * 2] + rsf[tid * 2 + 1];
            part[((long)z * TT + blockIdx.y * BM + tid) * 16 + blockIdx.x] = s;
        }
        return;
    }

    const float* adb = add ? add + (long)z * sAdd : nullptr;

#pragma unroll
    for (int mi = 0; mi < 2; mi++) {
        const int r0 = blockIdx.y * BM + wm * 32 + mi * 16 + (lane >> 2);
        float rowS[2];
        if (EPI == EPI_CTX) { rowS[0] = vv[r0]; rowS[1] = vv[r0 + 8]; }
#pragma unroll
        for (int ni = 0; ni < 8; ni++) {
            const int c = blockIdx.x * BN + wn * 64 + ni * 8 + (lane & 3) * 2;
#pragma unroll
            for (int p = 0; p < 2; p++) {
                const int r = r0 + p * 8;
                float v0 = acc[mi][ni][p * 2 + 0];
                float v1 = acc[mi][ni][p * 2 + 1];
                if (EPI == EPI_PROJ) {
                    v0 = fmaxf(v0, 0.f); v1 = fmaxf(v1, 0.f);
                    if (z == 0) { v0 *= vv[c]; v1 *= vv[c + 1]; }
                }
                if (EPI == EPI_CTX) {
                    float2 a2 = *(const float2*)(adb + (long)r * N + c);
                    v0 = v0 * rowS[p] + a2.x;
                    v1 = v1 * rowS[p] + a2.y;
                }
                if (EPI == EPI_BIAS_RELU) { v0 = fmaxf(v0 + vv[c], 0.f); v1 = fmaxf(v1 + vv[c + 1], 0.f); }
                if (EPI == EPI_BIAS)      { v0 += vv[c]; v1 += vv[c + 1]; }
                if (OUTH) {
                    __half* op = (__half*)Cbase + cBase + (long)r * N + c;
                    *(__half2*)op = __floats2half2_rn(v0, v1);
                } else {
                    float* op = (float*)Cbase + cBase + (long)r * N + c;
                    *(float2*)op = make_float2(v0, v1);
                }
            }
        }
    }
}

// ---------------- invs: qmask/rowsum ----------------
__global__ __launch_bounds__(256)
void invs_k(const float* __restrict__ part, const float* __restrict__ qmask,
            float* __restrict__ invs)
{
    const int i = blockIdx.x * 256 + threadIdx.x;
    float s = 0.f;
#pragma unroll
    for (int j = 0; j < 16; j++) s += part[(long)i * 16 + j];
    invs[i] = qmask[i] / s;
}

// ---------------- Q convert: f32 -> f16, plus fp32 copy to output ----------------
__global__ __launch_bounds__(256)
void convq_k(const float* __restrict__ in, __half* __restrict__ out, float* __restrict__ outc)
{
    const int i = blockIdx.x * 256 + threadIdx.x;
    float4 v = ((const float4*)in)[i];
    __half2* o = (__half2*)out + (long)i * 2;
    o[0] = __floats2half2_rn(v.x, v.y);
    o[1] = __floats2half2_rn(v.z, v.w);
    ((float4*)outc)[i] = v;
}

// ---------------- K convert + transpose ----------------
__global__ __launch_bounds__(256)
void convkt_k(const float* __restrict__ in, __half* __restrict__ lin, __half* __restrict__ tr,
              int R, int C, long sIn, long sOut)
{
    __shared__ float t[32][33];
    const long zi = (long)blockIdx.z * sIn, zo = (long)blockIdx.z * sOut;
    const int c0 = blockIdx.x * 32, r0 = blockIdx.y * 32;
    const int tx = threadIdx.x, ty = threadIdx.y;
#pragma unroll
    for (int i = ty; i < 32; i += 8) {
        float v = in[zi + (long)(r0 + i) * C + c0 + tx];
        t[i][tx] = v;
        lin[zi + (long)(r0 + i) * C + c0 + tx] = __float2half(v);
    }
    __syncthreads();
#pragma unroll
    for (int i = ty; i < 32; i += 8)
        tr[zo + (long)(c0 + i) * R + r0 + tx] = __float2half(t[tx][i]);
}

// ---------------- batched square transpose f32 -> f16: three matrices ----------------
__global__ __launch_bounds__(256)
void transp3_k(const float* __restrict__ s0, const float* __restrict__ s1,
               const float* __restrict__ s2,
               __half* __restrict__ d0, __half* __restrict__ d1, __half* __restrict__ d2)
{
    __shared__ float t[32][33];
    const float* in  = blockIdx.z == 0 ? s0 : (blockIdx.z == 1 ? s1 : s2);
    __half* out      = blockIdx.z == 0 ? d0 : (blockIdx.z == 1 ? d1 : d2);
    const int c0 = blockIdx.x * 32, r0 = blockIdx.y * 32;
    const int tx = threadIdx.x, ty = threadIdx.y;
#pragma unroll
    for (int i = ty; i < 32; i += 8)
        t[i][tx] = in[(long)(r0 + i) * CH + c0 + tx];
    __syncthreads();
#pragma unroll
    for (int i = ty; i < 32; i += 8)
        out[(long)(c0 + i) * CH + r0 + tx] = __float2half(t[tx][i]);
}

// ---------------- LayerNorm: fp32 in -> f16 out ----------------
__global__ __launch_bounds__(256)
void ln_k(const float* __restrict__ in, __half* __restrict__ out,
          const float* __restrict__ gamma, const float* __restrict__ beta)
{
    __shared__ float sh[8];
    const long row = blockIdx.x;
    const float* p = in + row * CH;
    const int tid = threadIdx.x, lane = tid & 31, w = tid >> 5;
    const int c = tid * 4;

    float4 xv = *(const float4*)(p + c);
    float s = xv.x + xv.y + xv.z + xv.w;
#pragma unroll
    for (int o = 16; o; o >>= 1) s += __shfl_xor_sync(0xffffffffu, s, o);
    if (lane == 0) sh[w] = s;
    __syncthreads();
    float tot = 0.f;
#pragma unroll
    for (int i = 0; i < 8; i++) tot += sh[i];
    const float mu = tot * (1.f / CH);

    float d0 = xv.x - mu, d1 = xv.y - mu, d2 = xv.z - mu, d3 = xv.w - mu;
    float q = d0 * d0 + d1 * d1 + d2 * d2 + d3 * d3;
#pragma unroll
    for (int o = 16; o; o >>= 1) q += __shfl_xor_sync(0xffffffffu, q, o);
    __syncthreads();
    if (lane == 0) sh[w] = q;
    __syncthreads();
    float vtot = 0.f;
#pragma unroll
    for (int i = 0; i < 8; i++) vtot += sh[i];
    const float rstd = rsqrtf(vtot * (1.f / CH) + 1e-6f);

    float4 g  = *(const float4*)(gamma + c);
    float4 be = *(const float4*)(beta + c);
    __half2* o2 = (__half2*)(out + row * CH + c);
    o2[0] = __floats2half2_rn(d0 * rstd * g.x + be.x, d1 * rstd * g.y + be.y);
    o2[1] = __floats2half2_rn(d2 * rstd * g.z + be.z, d3 * rstd * g.w + be.w);
}

// ---------------- launch ----------------
extern "C" void kernel_launch(void* const* d_in, const int* in_sizes, int n_in,
                              void* d_out, int out_size)
{
    const float* Q     = (const float*)d_in[0];
    const float* Kk    = (const float*)d_in[1];
    const float* kmask = (const float*)d_in[2];
    const float* qmask = (const float*)d_in[3];
    const float* u     = (const float*)d_in[4];
    const float* dd    = (const float*)d_in[5];
    const float* W1    = (const float*)d_in[6];
    const float* b1    = (const float*)d_in[7];
    const float* W2    = (const float*)d_in[8];
    const float* b2    = (const float*)d_in[9];
    const float* gamma = (const float*)d_in[10];
    const float* beta  = (const float*)d_in[11];

    __half *hQ, *hK, *hKT, *hUT, *hW1T, *hW2T, *f1h, *f2h, *hS, *hLN, *hH;
    float  *ctx, *part, *invs;
    cudaGetSymbolAddress((void**)&hQ,  g_hQ);
    cudaGetSymbolAddress((void**)&hK,  g_hK);
    cudaGetSymbolAddress((void**)&hKT, g_hKT);
    cudaGetSymbolAddress((void**)&hUT, g_hUT);
    cudaGetSymbolAddress((void**)&hW1T, g_hW1T);
    cudaGetSymbolAddress((void**)&hW2T, g_hW2T);
    cudaGetSymbolAddress((void**)&f1h, g_f1h);
    cudaGetSymbolAddress((void**)&f2h, g_f2h);
    cudaGetSymbolAddress((void**)&hS,  g_hS);
    cudaGetSymbolAddress((void**)&ctx, g_ctx);
    cudaGetSymbolAddress((void**)&hLN, g_hLN);
    cudaGetSymbolAddress((void**)&hH,  g_hH);
    cudaGetSymbolAddress((void**)&part, g_part);
    cudaGetSymbolAddress((void**)&invs, g_invs);

    const long TC  = (long)TT * CH;
    const long TTl = (long)TT * TT;

    float* out2 = (float*)d_out;
    float* outq = (float*)d_out;
    if ((long)out_size >= 2 * (long)NTC) out2 = (float*)d_out + NTC;

    cudaFuncSetAttribute(gemmvA<EPI_PROJ, true>,      cudaFuncAttributeMaxDynamicSharedMemorySize, SMEM_G);
    cudaFuncSetAttribute(gemmvA<EPI_EXP, true>,       cudaFuncAttributeMaxDynamicSharedMemorySize, SMEM_G);
    cudaFuncSetAttribute(gemmvA<EPI_CTX, false>,      cudaFuncAttributeMaxDynamicSharedMemorySize, SMEM_G);
    cudaFuncSetAttribute(gemmvA<EPI_BIAS_RELU, true>, cudaFuncAttributeMaxDynamicSharedMemorySize, SMEM_G);
    cudaFuncSetAttribute(gemmvA<EPI_BIAS, false>,     cudaFuncAttributeMaxDynamicSharedMemorySize, SMEM_G);

    // ---- conversions ----
    convq_k<<<NTC / 1024, 256>>>(Q, hQ, outq);                                        // 1
    convkt_k<<<dim3(CH / 32, TT / 32, BB), dim3(32, 8)>>>(Kk, hK, hKT, TT, CH, TC, TC); // 2
    transp3_k<<<dim3(CH / 32, CH / 32, 3), dim3(32, 8)>>>(u, W1, W2, hUT, hW1T, hW2T);  // 3

    // ---- 1+2) f1 = relu(Q@u)*d ; f2 = relu(K@u)  (merged, grid.z=2) ----             4
    gemmvA<EPI_PROJ, true><<<dim3(CH / BN, BB * TT / BM, 2), NTHR, SMEM_G>>>(
        hQ, hK, hUT, f1h, f2h, BB * TT, CH, CH, 0, 0, 0, dd, 0, nullptr, 0, 0.f, nullptr);

    // ---- 3) expS = exp((f1 @ f2^T)/32) masked -> f16, + row partial sums ----
    gemmvA<EPI_EXP, true><<<dim3(TT / BN, TT / BM, BB), NTHR, SMEM_G>>>(
        f1h, nullptr, f2h, hS, nullptr, TT, TT, CH, TC, TC, TTl, kmask, TT, nullptr, 0,
        1.0f / 32.0f, part);

    // ---- 4) invs = qmask / rowsum ----
    invs_k<<<BB * TT / 256, 256>>>(part, qmask, invs);

    // ---- 5) ctx = (expS @ K) * invs[row] + Q  (fp32 out) ----
    gemmvA<EPI_CTX, false><<<dim3(CH / BN, TT / BM, BB), NTHR, SMEM_G>>>(
        hS, nullptr, hKT, ctx, nullptr, TT, CH, TT, TTl, TC, TC, invs, TT, Q, TC, 0.f, nullptr);

    // ---- 6) LayerNorm -> f16 ----
    ln_k<<<BB * TT, 256>>>(ctx, hLN, gamma, beta);

    // ---- 7) h = relu(LN @ W1 + b1) -> f16 ----
    gemmvA<EPI_BIAS_RELU, true><<<dim3(CH / BN, BB * TT / BM, 1), NTHR, SMEM_G>>>(
        hLN, nullptr, hW1T, hH, nullptr, BB * TT, CH, CH, 0, 0, 0, b1, 0, nullptr, 0, 0.f, nullptr);

    // ---- 8) out2 = h @ W2 + b2 (fp32 out) ----
    gemmvA<EPI_BIAS, false><<<dim3(CH / BN, BB * TT / BM, 1), NTHR, SMEM_G>>>(
        hH, nullptr, hW2T, out2, nullptr, BB * TT, CH, CH, 0, 0, 0, b2, 0, nullptr, 0, 0.f, nullptr);
}

// round 15
// speedup vs baseline: 1.0544x; 1.0544x over previous
#include <cuda_runtime.h>
#include <cuda_fp16.h>
#include <math.h>
#include <stdint.h>

#define BB  8
#define TT  2048
#define CH  1024

#define NTC   (BB * TT * CH)              // 16,777,216
#define NTT   ((size_t)BB * TT * TT)      // 33,554,432

// ---------------- scratch (no allocations allowed) ----------------
__device__ __half g_hQ [NTC];
__device__ __half g_hK [NTC];
__device__ __half g_hKT[NTC];             // per-batch [CH][TT]
__device__ __half g_hUT [CH * CH];
__device__ __half g_hW1T[CH * CH];
__device__ __half g_hW2T[CH * CH];
__device__ __half g_f1h[NTC];
__device__ __half g_f2h[NTC];
__device__ __half g_hS [NTT];             // f16 exp(scores)
__device__ float  g_part[BB * TT * 16];
__device__ float  g_invs[BB * TT];
__device__ float  g_ctx[NTC];
__device__ __half g_hLN[NTC];
__device__ __half g_hH [NTC];

enum { EPI_PROJ = 0, EPI_EXP, EPI_CTX, EPI_BIAS_RELU, EPI_BIAS };

// ---------------- PTX helpers ----------------
__device__ __forceinline__ uint32_t smem_u32(const void* p) {
    uint32_t a;
    asm("{ .reg .u64 t; cvta.to.shared.u64 t, %1; cvt.u32.u64 %0, t; }" : "=r"(a) : "l"(p));
    return a;
}
__device__ __forceinline__ void ldsm4(uint32_t* r, uint32_t addr) {
    asm volatile("ldmatrix.sync.aligned.m8n8.x4.shared.b16 {%0,%1,%2,%3}, [%4];"
        : "=r"(r[0]), "=r"(r[1]), "=r"(r[2]), "=r"(r[3]) : "r"(addr));
}
__device__ __forceinline__ void mma_f16(float* d, const uint32_t* a, const uint32_t* b) {
    asm volatile(
        "mma.sync.aligned.m16n8k16.row.col.f32.f16.f16.f32 "
        "{%0,%1,%2,%3}, {%4,%5,%6,%7}, {%8,%9}, {%0,%1,%2,%3};"
        : "+f"(d[0]), "+f"(d[1]), "+f"(d[2]), "+f"(d[3])
        : "r"(a[0]), "r"(a[1]), "r"(a[2]), "r"(a[3]), "r"(b[0]), "r"(b[1]));
}
#define CP16(dst, src) \
    asm volatile("cp.async.cg.shared.global [%0], [%1], 16;" :: "r"(dst), "l"(src) : "memory")
#define CP_COMMIT()  asm volatile("cp.async.commit_group;" ::: "memory")
#define CP_WAIT1()   asm volatile("cp.async.wait_group 1;" ::: "memory")
#define CP_WAIT0()   asm volatile("cp.async.wait_group 0;" ::: "memory")

// swizzled offset within a k32 subtile: rows of 64B (32 halves), 16B column c (0..3)
__device__ __forceinline__ uint32_t swz(int row, int c) {
    return (uint32_t)(row * 64 + (((c) ^ ((row >> 1) & 3)) << 4));
}

// CTA tile 128x128, STAGE = K64 (two k32 subtiles), 3-stage cp.async ring,
// 8 warps (4m x 2n) of 32x64, 256 threads, 2 CTAs/SM.
#define BM 128
#define BN 128
#define A_BYTES (BM * 64)                 // 8192 per subtile
#define B_BYTES (BN * 64)                 // 8192 per subtile
#define SUBSTG  (A_BYTES + B_BYTES)       // 16384
#define STAGE   (2 * SUBSTG)              // 32768 (K=64)
#define SMEM_G  (3 * STAGE)               // 98304
#define NTHR    256

#define GEMM_SETUP()                                                           \
    extern __shared__ char smem[];                                             \
    const uint32_t sb = smem_u32(smem);                                        \
    const int tid = threadIdx.x, lane = tid & 31, warp = tid >> 5;             \
    const int wm = warp >> 1, wn = warp & 1;                                   \
    const int z = blockIdx.z;                                                  \
    uint32_t adst[2], bdst[2];                                                 \
    const __half* asrc[2];                                                     \
    const __half* bsrc[2];                                                     \
    _Pragma("unroll")                                                          \
    for (int i = 0; i < 2; i++) {                                              \
        int q = tid + i * NTHR, r = q >> 2, c = q & 3;                         \
        adst[i] = swz(r, c);                                                   \
        asrc[i] = Ap + (long)r * K + c * 8;                                    \
        bdst[i] = A_BYTES + swz(r, c);                                         \
        bsrc[i] = Bp + (long)r * K + c * 8;                                    \
    }                                                                          \
    const int q8 = lane >> 3, rr = lane & 7;                                   \
    const int rA = wm * 32 + (q8 & 1) * 8 + rr;                                \
    const int xA = (rA >> 1) & 3;                                              \
    const int cA = q8 >> 1;                                                    \
    const int rB = wn * 64 + (q8 >> 1) * 8 + rr;                               \
    const int xB = (rB >> 1) & 3;                                              \
    const int cB = q8 & 1;

// one stage = K64: two k32 subtiles, single commit
#define ISSUE(st)                                                              \
    do {                                                                       \
        const uint32_t _s = sb + ((st) % 3) * STAGE;                           \
        _Pragma("unroll")                                                      \
        for (int _sub = 0; _sub < 2; _sub++) {                                 \
            const long _ko = (long)(st) * 64 + _sub * 32;                      \
            const uint32_t _d = _s + _sub * SUBSTG;                            \
            CP16(_d + adst[0], asrc[0] + _ko);                                 \
            CP16(_d + adst[1], asrc[1] + _ko);                                 \
            CP16(_d + bdst[0], bsrc[0] + _ko);                                 \
            CP16(_d + bdst[1], bsrc[1] + _ko);                                 \
        }                                                                      \
        CP_COMMIT();                                                           \
    } while (0)

#define MAINLOOP()                                                             \
    ISSUE(0);                                                                  \
    ISSUE(1);                                                                  \
    const int nSt = K / 64;                                                    \
    for (int st = 0; st < nSt; st++) {                                         \
        if (st + 1 < nSt) CP_WAIT1(); else CP_WAIT0();                         \
        __syncthreads();                                                       \
        const uint32_t stbase = sb + (st % 3) * STAGE;                         \
        _Pragma("unroll")                                                      \
        for (int sub = 0; sub < 2; sub++) {                                    \
            const uint32_t sbase = stbase + sub * SUBSTG;                      \
            _Pragma("unroll")                                                  \
            for (int s = 0; s < 2; s++) {                                      \
                uint32_t af[2][4];                                             \
                _Pragma("unroll")                                              \
                for (int mi = 0; mi < 2; mi++)                                 \
                    ldsm4(af[mi], sbase + (uint32_t)((rA + mi * 16) * 64) +    \
                                  (uint32_t)((((2 * s + cA) ^ xA)) << 4));     \
                _Pragma("unroll")                                              \
                for (int nip = 0; nip < 4; nip++) {                            \
                    uint32_t t4[4];                                            \
                    ldsm4(t4, sbase + A_BYTES + (uint32_t)((rB + nip * 16) * 64) + \
                              (uint32_t)((((2 * s + cB) ^ xB)) << 4));         \
                    _Pragma("unroll")                                          \
                    for (int mi = 0; mi < 2; mi++) mma_f16(acc[mi][2 * nip],     af[mi], &t4[0]); \
                    _Pragma("unroll")                                          \
                    for (int mi = 0; mi < 2; mi++) mma_f16(acc[mi][2 * nip + 1], af[mi], &t4[2]); \
                }                                                              \
            }                                                                  \
        }                                                                      \
        if (st + 2 < nSt) ISSUE(st + 2);                                       \
    }

// ---------------- f16-in / f32-acc GEMM, fused epilogues ----------------
template <int EPI, bool OUTH>
__global__ void __launch_bounds__(NTHR, 2)
gemmv7(const __half* __restrict__ A, const __half* __restrict__ A2,
       const __half* __restrict__ B, void* __restrict__ Cv, void* __restrict__ Cv2,
       int M, int N, int K, long sA, long sB, long sC,
       const float* __restrict__ vec, long sVec,
       const float* __restrict__ add, long sAdd, float scale,
       float* __restrict__ part)
{
    const __half* Abase = A;
    void* Cbase = Cv;
    if (EPI == EPI_PROJ && blockIdx.z == 1) { Abase = A2; Cbase = Cv2; }
    const __half* Ap = Abase + (long)blockIdx.z * sA + (long)(blockIdx.y * BM) * K;
    const __half* Bp = B + (long)blockIdx.z * sB + (long)(blockIdx.x * BN) * K;

    GEMM_SETUP();

    float acc[2][8][4];
#pragma unroll
    for (int mi = 0; mi < 2; mi++)
#pragma unroll
        for (int ni = 0; ni < 8; ni++)
#pragma unroll
            for (int e = 0; e < 4; e++) acc[mi][ni][e] = 0.f;

    MAINLOOP();

    const float* vv = vec ? vec + (long)z * sVec : nullptr;
    const long cBase = (long)z * sC;

    if (EPI == EPI_EXP) {
        float rsl[2][2] = {{0.f, 0.f}, {0.f, 0.f}};
#pragma unroll
        for (int mi = 0; mi < 2; mi++) {
            const int r0 = blockIdx.y * BM + wm * 32 + mi * 16 + (lane >> 2);
#pragma unroll
            for (int ni = 0; ni < 8; ni++) {
                const int c = blockIdx.x * BN + wn * 64 + ni * 8 + (lane & 3) * 2;
                const float m0 = vv[c], m1 = vv[c + 1];
#pragma unroll
                for (int p = 0; p < 2; p++) {
                    const int r = r0 + p * 8;
                    float e0 = (m0 == 0.f) ? 0.f : __expf(acc[mi][ni][p * 2 + 0] * scale);
                    float e1 = (m1 == 0.f) ? 0.f : __expf(acc[mi][ni][p * 2 + 1] * scale);
                    __half2 h = __floats2half2_rn(e0, e1);
                    *(__half2*)((__half*)Cv + cBase + (long)r * N + c) = h;
                    float2 fr = __half22float2(h);
                    rsl[mi][p] += fr.x + fr.y;
                }
            }
        }
        float* rsf = (float*)(smem + (nSt % 3) * STAGE);
#pragma unroll
        for (int mi = 0; mi < 2; mi++)
#pragma unroll
            for (int p = 0; p < 2; p++) {
                float s = rsl[mi][p];
                s += __shfl_xor_sync(0xffffffffu, s, 1);
                s += __shfl_xor_sync(0xffffffffu, s, 2);
                if ((lane & 3) == 0)
                    rsf[(wm * 32 + mi * 16 + p * 8 + (lane >> 2)) * 2 + wn] = s;
            }
        __syncthreads();
        if (tid < BM) {
            float s = rsf[tid * 2] + rsf[tid * 2 + 1];
            part[((long)z * TT + blockIdx.y * BM + tid) * 16 + blockIdx.x] = s;
        }
        return;
    }

    const float* adb = add ? add + (long)z * sAdd : nullptr;

#pragma unroll
    for (int mi = 0; mi < 2; mi++) {
        const int r0 = blockIdx.y * BM + wm * 32 + mi * 16 + (lane >> 2);
        float rowS[2];
        if (EPI == EPI_CTX) { rowS[0] = vv[r0]; rowS[1] = vv[r0 + 8]; }
#pragma unroll
        for (int ni = 0; ni < 8; ni++) {
            const int c = blockIdx.x * BN + wn * 64 + ni * 8 + (lane & 3) * 2;
#pragma unroll
            for (int p = 0; p < 2; p++) {
                const int r = r0 + p * 8;
                float v0 = acc[mi][ni][p * 2 + 0];
                float v1 = acc[mi][ni][p * 2 + 1];
                if (EPI == EPI_PROJ) {
                    v0 = fmaxf(v0, 0.f); v1 = fmaxf(v1, 0.f);
                    if (z == 0) { v0 *= vv[c]; v1 *= vv[c + 1]; }
                }
                if (EPI == EPI_CTX) {
                    float2 a2 = *(const float2*)(adb + (long)r * N + c);
                    v0 = v0 * rowS[p] + a2.x;
                    v1 = v1 * rowS[p] + a2.y;
                }
                if (EPI == EPI_BIAS_RELU) { v0 = fmaxf(v0 + vv[c], 0.f); v1 = fmaxf(v1 + vv[c + 1], 0.f); }
                if (EPI == EPI_BIAS)      { v0 += vv[c]; v1 += vv[c + 1]; }
                if (OUTH) {
                    __half* op = (__half*)Cbase + cBase + (long)r * N + c;
                    *(__half2*)op = __floats2half2_rn(v0, v1);
                } else {
                    float* op = (float*)Cbase + cBase + (long)r * N + c;
                    *(float2*)op = make_float2(v0, v1);
                }
            }
        }
    }
}

// ---------------- invs: qmask/rowsum ----------------
__global__ __launch_bounds__(256)
void invs_k(const float* __restrict__ part, const float* __restrict__ qmask,
            float* __restrict__ invs)
{
    const int i = blockIdx.x * 256 + threadIdx.x;
    float s = 0.f;
#pragma unroll
    for (int j = 0; j < 16; j++) s += part[(long)i * 16 + j];
    invs[i] = qmask[i] / s;
}

// ---------------- Q convert: f32 -> f16, plus fp32 copy to output ----------------
__global__ __launch_bounds__(256)
void convq_k(const float* __restrict__ in, __half* __restrict__ out, float* __restrict__ outc)
{
    const int i = blockIdx.x * 256 + threadIdx.x;
    float4 v = ((const float4*)in)[i];
    __half2* o = (__half2*)out + (long)i * 2;
    o[0] = __floats2half2_rn(v.x, v.y);
    o[1] = __floats2half2_rn(v.z, v.w);
    ((float4*)outc)[i] = v;
}

// ---------------- K convert + transpose ----------------
__global__ __launch_bounds__(256)
void convkt_k(const float* __restrict__ in, __half* __restrict__ lin, __half* __restrict__ tr,
              int R, int C, long sIn, long sOut)
{
    __shared__ float t[32][33];
    const long zi = (long)blockIdx.z * sIn, zo = (long)blockIdx.z * sOut;
    const int c0 = blockIdx.x * 32, r0 = blockIdx.y * 32;
    const int tx = threadIdx.x, ty = threadIdx.y;
#pragma unroll
    for (int i = ty; i < 32; i += 8) {
        float v = in[zi + (long)(r0 + i) * C + c0 + tx];
        t[i][tx] = v;
        lin[zi + (long)(r0 + i) * C + c0 + tx] = __float2half(v);
    }
    __syncthreads();
#pragma unroll
    for (int i = ty; i < 32; i += 8)
        tr[zo + (long)(c0 + i) * R + r0 + tx] = __float2half(t[tx][i]);
}

// ---------------- batched square transpose f32 -> f16: three matrices ----------------
__global__ __launch_bounds__(256)
void transp3_k(const float* __restrict__ s0, const float* __restrict__ s1,
               const float* __restrict__ s2,
               __half* __restrict__ d0, __half* __restrict__ d1, __half* __restrict__ d2)
{
    __shared__ float t[32][33];
    const float* in  = blockIdx.z == 0 ? s0 : (blockIdx.z == 1 ? s1 : s2);
    __half* out      = blockIdx.z == 0 ? d0 : (blockIdx.z == 1 ? d1 : d2);
    const int c0 = blockIdx.x * 32, r0 = blockIdx.y * 32;
    const int tx = threadIdx.x, ty = threadIdx.y;
#pragma unroll
    for (int i = ty; i < 32; i += 8)
        t[i][tx] = in[(long)(r0 + i) * CH + c0 + tx];
    __syncthreads();
#pragma unroll
    for (int i = ty; i < 32; i += 8)
        out[(long)(c0 + i) * CH + r0 + tx] = __float2half(t[tx][i]);
}

// ---------------- LayerNorm: fp32 in -> f16 out ----------------
__global__ __launch_bounds__(256)
void ln_k(const float* __restrict__ in, __half* __restrict__ out,
          const float* __restrict__ gamma, const float* __restrict__ beta)
{
    __shared__ float sh[8];
    const long row = blockIdx.x;
    const float* p = in + row * CH;
    const int tid = threadIdx.x, lane = tid & 31, w = tid >> 5;
    const int c = tid * 4;

    float4 xv = *(const float4*)(p + c);
    float s = xv.x + xv.y + xv.z + xv.w;
#pragma unroll
    for (int o = 16; o; o >>= 1) s += __shfl_xor_sync(0xffffffffu, s, o);
    if (lane == 0) sh[w] = s;
    __syncthreads();
    float tot = 0.f;
#pragma unroll
    for (int i = 0; i < 8; i++) tot += sh[i];
    const float mu = tot * (1.f / CH);

    float d0 = xv.x - mu, d1 = xv.y - mu, d2 = xv.z - mu, d3 = xv.w - mu;
    float q = d0 * d0 + d1 * d1 + d2 * d2 + d3 * d3;
#pragma unroll
    for (int o = 16; o; o >>= 1) q += __shfl_xor_sync(0xffffffffu, q, o);
    __syncthreads();
    if (lane == 0) sh[w] = q;
    __syncthreads();
    float vtot = 0.f;
#pragma unroll
    for (int i = 0; i < 8; i++) vtot += sh[i];
    const float rstd = rsqrtf(vtot * (1.f / CH) + 1e-6f);

    float4 g  = *(const float4*)(gamma + c);
    float4 be = *(const float4*)(beta + c);
    __half2* o2 = (__half2*)(out + row * CH + c);
    o2[0] = __floats2half2_rn(d0 * rstd * g.x + be.x, d1 * rstd * g.y + be.y);
    o2[1] = __floats2half2_rn(d2 * rstd * g.z + be.z, d3 * rstd * g.w + be.w);
}

// ---------------- launch ----------------
extern "C" void kernel_launch(void* const* d_in, const int* in_sizes, int n_in,
                              void* d_out, int out_size)
{
    const float* Q     = (const float*)d_in[0];
    const float* Kk    = (const float*)d_in[1];
    const float* kmask = (const float*)d_in[2];
    const float* qmask = (const float*)d_in[3];
    const float* u     = (const float*)d_in[4];
    const float* dd    = (const float*)d_in[5];
    const float* W1    = (const float*)d_in[6];
    const float* b1    = (const float*)d_in[7];
    const float* W2    = (const float*)d_in[8];
    const float* b2    = (const float*)d_in[9];
    const float* gamma = (const float*)d_in[10];
    const float* beta  = (const float*)d_in[11];

    __half *hQ, *hK, *hKT, *hUT, *hW1T, *hW2T, *f1h, *f2h, *hS, *hLN, *hH;
    float  *ctx, *part, *invs;
    cudaGetSymbolAddress((void**)&hQ,  g_hQ);
    cudaGetSymbolAddress((void**)&hK,  g_hK);
    cudaGetSymbolAddress((void**)&hKT, g_hKT);
    cudaGetSymbolAddress((void**)&hUT, g_hUT);
    cudaGetSymbolAddress((void**)&hW1T, g_hW1T);
    cudaGetSymbolAddress((void**)&hW2T, g_hW2T);
    cudaGetSymbolAddress((void**)&f1h, g_f1h);
    cudaGetSymbolAddress((void**)&f2h, g_f2h);
    cudaGetSymbolAddress((void**)&hS,  g_hS);
    cudaGetSymbolAddress((void**)&ctx, g_ctx);
    cudaGetSymbolAddress((void**)&hLN, g_hLN);
    cudaGetSymbolAddress((void**)&hH,  g_hH);
    cudaGetSymbolAddress((void**)&part, g_part);
    cudaGetSymbolAddress((void**)&invs, g_invs);

    const long TC  = (long)TT * CH;
    const long TTl = (long)TT * TT;

    float* out2 = (float*)d_out;
    float* outq = (float*)d_out;
    if ((long)out_size >= 2 * (long)NTC) out2 = (float*)d_out + NTC;

    cudaFuncSetAttribute(gemmv7<EPI_PROJ, true>,      cudaFuncAttributeMaxDynamicSharedMemorySize, SMEM_G);
    cudaFuncSetAttribute(gemmv7<EPI_EXP, true>,       cudaFuncAttributeMaxDynamicSharedMemorySize, SMEM_G);
    cudaFuncSetAttribute(gemmv7<EPI_CTX, false>,      cudaFuncAttributeMaxDynamicSharedMemorySize, SMEM_G);
    cudaFuncSetAttribute(gemmv7<EPI_BIAS_RELU, true>, cudaFuncAttributeMaxDynamicSharedMemorySize, SMEM_G);
    cudaFuncSetAttribute(gemmv7<EPI_BIAS, false>,     cudaFuncAttributeMaxDynamicSharedMemorySize, SMEM_G);

    // ---- conversions ----
    convq_k<<<NTC / 1024, 256>>>(Q, hQ, outq);                                        // 1
    convkt_k<<<dim3(CH / 32, TT / 32, BB), dim3(32, 8)>>>(Kk, hK, hKT, TT, CH, TC, TC); // 2
    transp3_k<<<dim3(CH / 32, CH / 32, 3), dim3(32, 8)>>>(u, W1, W2, hUT, hW1T, hW2T);  // 3

    // ---- 1+2) f1 = relu(Q@u)*d ; f2 = relu(K@u)  (merged, grid.z=2) ----             4
    gemmv7<EPI_PROJ, true><<<dim3(CH / BN, BB * TT / BM, 2), NTHR, SMEM_G>>>(
        hQ, hK, hUT, f1h, f2h, BB * TT, CH, CH, 0, 0, 0, dd, 0, nullptr, 0, 0.f, nullptr);

    // ---- 3) expS = exp((f1 @ f2^T)/32) masked -> f16, + row partial sums ----
    gemmv7<EPI_EXP, true><<<dim3(TT / BN, TT / BM, BB), NTHR, SMEM_G>>>(
        f1h, nullptr, f2h, hS, nullptr, TT, TT, CH, TC, TC, TTl, kmask, TT, nullptr, 0,
        1.0f / 32.0f, part);

    // ---- 4) invs = qmask / rowsum ----
    invs_k<<<BB * TT / 256, 256>>>(part, qmask, invs);

    // ---- 5) ctx = (expS @ K) * invs[row] + Q  (fp32 out) ----
    gemmv7<EPI_CTX, false><<<dim3(CH / BN, TT / BM, BB), NTHR, SMEM_G>>>(
        hS, nullptr, hKT, ctx, nullptr, TT, CH, TT, TTl, TC, TC, invs, TT, Q, TC, 0.f, nullptr);

    // ---- 6) LayerNorm -> f16 ----
    ln_k<<<BB * TT, 256>>>(ctx, hLN, gamma, beta);

    // ---- 7) h = relu(LN @ W1 + b1) -> f16 ----
    gemmv7<EPI_BIAS_RELU, true><<<dim3(CH / BN, BB * TT / BM, 1), NTHR, SMEM_G>>>(
        hLN, nullptr, hW1T, hH, nullptr, BB * TT, CH, CH, 0, 0, 0, b1, 0, nullptr, 0, 0.f, nullptr);

    // ---- 8) out2 = h @ W2 + b2 (fp32 out) ----
    gemmv7<EPI_BIAS, false><<<dim3(CH / BN, BB * TT / BM, 1), NTHR, SMEM_G>>>(
        hH, nullptr, hW2T, out2, nullptr, BB * TT, CH, CH, 0, 0, 0, b2, 0, nullptr, 0, 0.f, nullptr);
}

// round 16
// speedup vs baseline: 1.0682x; 1.0131x over previous
#include <cuda_runtime.h>
#include <cuda_fp16.h>
#include <math.h>
#include <stdint.h>

#define BB  8
#define TT  2048
#define CH  1024

#define NTC   (BB * TT * CH)              // 16,777,216
#define NTT   ((size_t)BB * TT * TT)      // 33,554,432

// ---------------- scratch (no allocations allowed) ----------------
__device__ __half g_hQ [NTC];
__device__ __half g_hK [NTC];
__device__ __half g_hKT[NTC];             // per-batch [CH][TT]
__device__ __half g_hUT [CH * CH];
__device__ __half g_hW1T[CH * CH];
__device__ __half g_hW2T[CH * CH];
__device__ __half g_f1h[NTC];             // proj f1; later reused as f16 ctx
__device__ __half g_f2h[NTC];
__device__ __half g_hS [NTT];             // f16 exp(scores)
__device__ float  g_part[BB * TT * 16];
__device__ float  g_invs[BB * TT];
__device__ float  g_musig[BB * TT * 2];   // per-row (mu, rstd)
__device__ __half g_hLN[NTC];
__device__ __half g_hH [NTC];

enum { EPI_PROJ = 0, EPI_EXP, EPI_CTX, EPI_BIAS_RELU, EPI_BIAS };

// ---------------- PTX helpers ----------------
__device__ __forceinline__ uint32_t smem_u32(const void* p) {
    uint32_t a;
    asm("{ .reg .u64 t; cvta.to.shared.u64 t, %1; cvt.u32.u64 %0, t; }" : "=r"(a) : "l"(p));
    return a;
}
__device__ __forceinline__ void ldsm4(uint32_t* r, uint32_t addr) {
    asm volatile("ldmatrix.sync.aligned.m8n8.x4.shared.b16 {%0,%1,%2,%3}, [%4];"
        : "=r"(r[0]), "=r"(r[1]), "=r"(r[2]), "=r"(r[3]) : "r"(addr));
}
__device__ __forceinline__ void mma_f16(float* d, const uint32_t* a, const uint32_t* b) {
    asm volatile(
        "mma.sync.aligned.m16n8k16.row.col.f32.f16.f16.f32 "
        "{%0,%1,%2,%3}, {%4,%5,%6,%7}, {%8,%9}, {%0,%1,%2,%3};"
        : "+f"(d[0]), "+f"(d[1]), "+f"(d[2]), "+f"(d[3])
        : "r"(a[0]), "r"(a[1]), "r"(a[2]), "r"(a[3]), "r"(b[0]), "r"(b[1]));
}
#define CP16(dst, src) \
    asm volatile("cp.async.cg.shared.global [%0], [%1], 16;" :: "r"(dst), "l"(src) : "memory")
#define CP_COMMIT()  asm volatile("cp.async.commit_group;" ::: "memory")
#define CP_WAIT1()   asm volatile("cp.async.wait_group 1;" ::: "memory")
#define CP_WAIT0()   asm volatile("cp.async.wait_group 0;" ::: "memory")

// swizzled offset within a k32 subtile: rows of 64B (32 halves), 16B column c (0..3)
__device__ __forceinline__ uint32_t swz(int row, int c) {
    return (uint32_t)(row * 64 + (((c) ^ ((row >> 1) & 3)) << 4));
}

// CTA tile 128x128, STAGE = K64 (two k32 subtiles), 3-stage cp.async ring,
// 8 warps (4m x 2n) of 32x64, 256 threads, 2 CTAs/SM.
#define BM 128
#define BN 128
#define A_BYTES (BM * 64)                 // 8192 per subtile
#define B_BYTES (BN * 64)                 // 8192 per subtile
#define SUBSTG  (A_BYTES + B_BYTES)       // 16384
#define STAGE   (2 * SUBSTG)              // 32768 (K=64)
#define SMEM_G  (3 * STAGE)               // 98304
#define NTHR    256

#define GEMM_SETUP()                                                           \
    extern __shared__ char smem[];                                             \
    const uint32_t sb = smem_u32(smem);                                        \
    const int tid = threadIdx.x, lane = tid & 31, warp = tid >> 5;             \
    const int wm = warp >> 1, wn = warp & 1;                                   \
    const int z = blockIdx.z;                                                  \
    uint32_t adst[2], bdst[2];                                                 \
    const __half* asrc[2];                                                     \
    const __half* bsrc[2];                                                     \
    _Pragma("unroll")                                                          \
    for (int i = 0; i < 2; i++) {                                              \
        int q = tid + i * NTHR, r = q >> 2, c = q & 3;                         \
        adst[i] = swz(r, c);                                                   \
        asrc[i] = Ap + (long)r * K + c * 8;                                    \
        bdst[i] = A_BYTES + swz(r, c);                                         \
        bsrc[i] = Bp + (long)r * K + c * 8;                                    \
    }                                                                          \
    const int q8 = lane >> 3, rr = lane & 7;                                   \
    const int rA = wm * 32 + (q8 & 1) * 8 + rr;                                \
    const int xA = (rA >> 1) & 3;                                              \
    const int cA = q8 >> 1;                                                    \
    const int rB = wn * 64 + (q8 >> 1) * 8 + rr;                               \
    const int xB = (rB >> 1) & 3;                                              \
    const int cB = q8 & 1;

// one stage = K64: two k32 subtiles, single commit
#define ISSUE(st)                                                              \
    do {                                                                       \
        const uint32_t _s = sb + ((st) % 3) * STAGE;                           \
        _Pragma("unroll")                                                      \
        for (int _sub = 0; _sub < 2; _sub++) {                                 \
            const long _ko = (long)(st) * 64 + _sub * 32;                      \
            const uint32_t _d = _s + _sub * SUBSTG;                            \
            CP16(_d + adst[0], asrc[0] + _ko);                                 \
            CP16(_d + adst[1], asrc[1] + _ko);                                 \
            CP16(_d + bdst[0], bsrc[0] + _ko);                                 \
            CP16(_d + bdst[1], bsrc[1] + _ko);                                 \
        }                                                                      \
        CP_COMMIT();                                                           \
    } while (0)

#define MAINLOOP()                                                             \
    ISSUE(0);                                                                  \
    ISSUE(1);                                                                  \
    const int nSt = K / 64;                                                    \
    for (int st = 0; st < nSt; st++) {                                         \
        if (st + 1 < nSt) CP_WAIT1(); else CP_WAIT0();                         \
        __syncthreads();                                                       \
        const uint32_t stbase = sb + (st % 3) * STAGE;                         \
        _Pragma("unroll")                                                      \
        for (int sub = 0; sub < 2; sub++) {                                    \
            const uint32_t sbase = stbase + sub * SUBSTG;                      \
            _Pragma("unroll")                                                  \
            for (int s = 0; s < 2; s++) {                                      \
                uint32_t af[2][4];                                             \
                _Pragma("unroll")                                              \
                for (int mi = 0; mi < 2; mi++)                                 \
                    ldsm4(af[mi], sbase + (uint32_t)((rA + mi * 16) * 64) +    \
                                  (uint32_t)((((2 * s + cA) ^ xA)) << 4));     \
                _Pragma("unroll")                                              \
                for (int nip = 0; nip < 4; nip++) {                            \
                    uint32_t t4[4];                                            \
                    ldsm4(t4, sbase + A_BYTES + (uint32_t)((rB + nip * 16) * 64) + \
                              (uint32_t)((((2 * s + cB) ^ xB)) << 4));         \
                    _Pragma("unroll")                                          \
                    for (int mi = 0; mi < 2; mi++) mma_f16(acc[mi][2 * nip],     af[mi], &t4[0]); \
                    _Pragma("unroll")                                          \
                    for (int mi = 0; mi < 2; mi++) mma_f16(acc[mi][2 * nip + 1], af[mi], &t4[2]); \
                }                                                              \
            }                                                                  \
        }                                                                      \
        if (st + 2 < nSt) ISSUE(st + 2);                                       \
    }

// ---------------- f16-in / f32-acc GEMM, fused epilogues ----------------
template <int EPI, bool OUTH>
__global__ void __launch_bounds__(NTHR, 2)
gemmv7(const __half* __restrict__ A, const __half* __restrict__ A2,
       const __half* __restrict__ B, void* __restrict__ Cv, void* __restrict__ Cv2,
       int M, int N, int K, long sA, long sB, long sC,
       const float* __restrict__ vec, long sVec,
       const float* __restrict__ add, long sAdd, float scale,
       float* __restrict__ part)
{
    const __half* Abase = A;
    void* Cbase = Cv;
    if (EPI == EPI_PROJ && blockIdx.z == 1) { Abase = A2; Cbase = Cv2; }
    const __half* Ap = Abase + (long)blockIdx.z * sA + (long)(blockIdx.y * BM) * K;
    const __half* Bp = B + (long)blockIdx.z * sB + (long)(blockIdx.x * BN) * K;

    GEMM_SETUP();

    float acc[2][8][4];
#pragma unroll
    for (int mi = 0; mi < 2; mi++)
#pragma unroll
        for (int ni = 0; ni < 8; ni++)
#pragma unroll
            for (int e = 0; e < 4; e++) acc[mi][ni][e] = 0.f;

    MAINLOOP();

    const float* vv = vec ? vec + (long)z * sVec : nullptr;
    const long cBase = (long)z * sC;

    if (EPI == EPI_EXP) {
        float rsl[2][2] = {{0.f, 0.f}, {0.f, 0.f}};
#pragma unroll
        for (int mi = 0; mi < 2; mi++) {
            const int r0 = blockIdx.y * BM + wm * 32 + mi * 16 + (lane >> 2);
#pragma unroll
            for (int ni = 0; ni < 8; ni++) {
                const int c = blockIdx.x * BN + wn * 64 + ni * 8 + (lane & 3) * 2;
                const float m0 = vv[c], m1 = vv[c + 1];
#pragma unroll
                for (int p = 0; p < 2; p++) {
                    const int r = r0 + p * 8;
                    float e0 = (m0 == 0.f) ? 0.f : __expf(acc[mi][ni][p * 2 + 0] * scale);
                    float e1 = (m1 == 0.f) ? 0.f : __expf(acc[mi][ni][p * 2 + 1] * scale);
                    __half2 h = __floats2half2_rn(e0, e1);
                    *(__half2*)((__half*)Cv + cBase + (long)r * N + c) = h;
                    float2 fr = __half22float2(h);
                    rsl[mi][p] += fr.x + fr.y;
                }
            }
        }
        float* rsf = (float*)(smem + (nSt % 3) * STAGE);
#pragma unroll
        for (int mi = 0; mi < 2; mi++)
#pragma unroll
            for (int p = 0; p < 2; p++) {
                float s = rsl[mi][p];
                s += __shfl_xor_sync(0xffffffffu, s, 1);
                s += __shfl_xor_sync(0xffffffffu, s, 2);
                if ((lane & 3) == 0)
                    rsf[(wm * 32 + mi * 16 + p * 8 + (lane >> 2)) * 2 + wn] = s;
            }
        __syncthreads();
        if (tid < BM) {
            float s = rsf[tid * 2] + rsf[tid * 2 + 1];
            part[((long)z * TT + blockIdx.y * BM + tid) * 16 + blockIdx.x] = s;
        }
        return;
    }

    if (EPI == EPI_CTX) {
        // ctx = acc*invs[row] + Q  -> f16; accumulate per-row sum & sumsq of the
        // f16-rounded values (self-consistent with the LN that follows).
        const float* adb = add + (long)z * sAdd;
        float s1l[2][2] = {{0.f, 0.f}, {0.f, 0.f}};
        float s2l[2][2] = {{0.f, 0.f}, {0.f, 0.f}};
#pragma unroll
        for (int mi = 0; mi < 2; mi++) {
            const int r0 = blockIdx.y * BM + wm * 32 + mi * 16 + (lane >> 2);
            const float rowS[2] = { vv[r0], vv[r0 + 8] };
#pragma unroll
            for (int ni = 0; ni < 8; ni++) {
                const int c = blockIdx.x * BN + wn * 64 + ni * 8 + (lane & 3) * 2;
#pragma unroll
                for (int p = 0; p < 2; p++) {
                    const int r = r0 + p * 8;
                    float2 a2 = *(const float2*)(adb + (long)r * N + c);
                    float v0 = acc[mi][ni][p * 2 + 0] * rowS[p] + a2.x;
                    float v1 = acc[mi][ni][p * 2 + 1] * rowS[p] + a2.y;
                    __half2 h = __floats2half2_rn(v0, v1);
                    *(__half2*)((__half*)Cv + cBase + (long)r * N + c) = h;
                    float2 fr = __half22float2(h);
                    s1l[mi][p] += fr.x + fr.y;
                    s2l[mi][p] += fr.x * fr.x + fr.y * fr.y;
                }
            }
        }
        float* rsf = (float*)(smem + (nSt % 3) * STAGE);
        float* rsq = rsf + 256;
#pragma unroll
        for (int mi = 0; mi < 2; mi++)
#pragma unroll
            for (int p = 0; p < 2; p++) {
                float s = s1l[mi][p], q = s2l[mi][p];
                s += __shfl_xor_sync(0xffffffffu, s, 1);
                s += __shfl_xor_sync(0xffffffffu, s, 2);
                q += __shfl_xor_sync(0xffffffffu, q, 1);
                q += __shfl_xor_sync(0xffffffffu, q, 2);
                if ((lane & 3) == 0) {
                    const int rl = wm * 32 + mi * 16 + p * 8 + (lane >> 2);
                    rsf[rl * 2 + wn] = s;
                    rsq[rl * 2 + wn] = q;
                }
            }
        __syncthreads();
        if (tid < BM) {
            const long prow = ((long)z * TT + blockIdx.y * BM + tid) * 16 + blockIdx.x * 2;
            part[prow + 0] = rsf[tid * 2] + rsf[tid * 2 + 1];
            part[prow + 1] = rsq[tid * 2] + rsq[tid * 2 + 1];
        }
        return;
    }

    const float* adb = add ? add + (long)z * sAdd : nullptr;

#pragma unroll
    for (int mi = 0; mi < 2; mi++) {
        const int r0 = blockIdx.y * BM + wm * 32 + mi * 16 + (lane >> 2);
#pragma unroll
        for (int ni = 0; ni < 8; ni++) {
            const int c = blockIdx.x * BN + wn * 64 + ni * 8 + (lane & 3) * 2;
#pragma unroll
            for (int p = 0; p < 2; p++) {
                const int r = r0 + p * 8;
                float v0 = acc[mi][ni][p * 2 + 0];
                float v1 = acc[mi][ni][p * 2 + 1];
                if (EPI == EPI_PROJ) {
                    v0 = fmaxf(v0, 0.f); v1 = fmaxf(v1, 0.f);
                    if (z == 0) { v0 *= vv[c]; v1 *= vv[c + 1]; }
                }
                if (EPI == EPI_BIAS_RELU) { v0 = fmaxf(v0 + vv[c], 0.f); v1 = fmaxf(v1 + vv[c + 1], 0.f); }
                if (EPI == EPI_BIAS)      { v0 += vv[c]; v1 += vv[c + 1]; }
                if (OUTH) {
                    __half* op = (__half*)Cbase + cBase + (long)r * N + c;
                    *(__half2*)op = __floats2half2_rn(v0, v1);
                } else {
                    float* op = (float*)Cbase + cBase + (long)r * N + c;
                    *(float2*)op = make_float2(v0, v1);
                }
            }
        }
    }
}

// ---------------- invs: qmask/rowsum ----------------
__global__ __launch_bounds__(256)
void invs_k(const float* __restrict__ part, const float* __restrict__ qmask,
            float* __restrict__ invs)
{
    const int i = blockIdx.x * 256 + threadIdx.x;
    float s = 0.f;
#pragma unroll
    for (int j = 0; j < 16; j++) s += part[(long)i * 16 + j];
    invs[i] = qmask[i] / s;
}

// ---------------- musig: per-row mean & rstd from ctx partials ----------------
__global__ __launch_bounds__(256)
void musig_k(const float* __restrict__ part, float* __restrict__ musig)
{
    const int i = blockIdx.x * 256 + threadIdx.x;
    float s = 0.f, q = 0.f;
#pragma unroll
    for (int j = 0; j < 8; j++) {
        s += part[(long)i * 16 + j * 2 + 0];
        q += part[(long)i * 16 + j * 2 + 1];
    }
    const float mu = s * (1.f / CH);
    const float var = q * (1.f / CH) - mu * mu;
    musig[i * 2 + 0] = mu;
    musig[i * 2 + 1] = rsqrtf(var + 1e-6f);
}

// ---------------- Q convert: f32 -> f16, plus fp32 copy to output ----------------
__global__ __launch_bounds__(256)
void convq_k(const float* __restrict__ in, __half* __restrict__ out, float* __restrict__ outc)
{
    const int i = blockIdx.x * 256 + threadIdx.x;
    float4 v = ((const float4*)in)[i];
    __half2* o = (__half2*)out + (long)i * 2;
    o[0] = __floats2half2_rn(v.x, v.y);
    o[1] = __floats2half2_rn(v.z, v.w);
    ((float4*)outc)[i] = v;
}

// ---------------- K convert + transpose ----------------
__global__ __launch_bounds__(256)
void convkt_k(const float* __restrict__ in, __half* __restrict__ lin, __half* __restrict__ tr,
              int R, int C, long sIn, long sOut)
{
    __shared__ float t[32][33];
    const long zi = (long)blockIdx.z * sIn, zo = (long)blockIdx.z * sOut;
    const int c0 = blockIdx.x * 32, r0 = blockIdx.y * 32;
    const int tx = threadIdx.x, ty = threadIdx.y;
#pragma unroll
    for (int i = ty; i < 32; i += 8) {
        float v = in[zi + (long)(r0 + i) * C + c0 + tx];
        t[i][tx] = v;
        lin[zi + (long)(r0 + i) * C + c0 + tx] = __float2half(v);
    }
    __syncthreads();
#pragma unroll
    for (int i = ty; i < 32; i += 8)
        tr[zo + (long)(c0 + i) * R + r0 + tx] = __float2half(t[tx][i]);
}

// ---------------- batched square transpose f32 -> f16: three matrices ----------------
__global__ __launch_bounds__(256)
void transp3_k(const float* __restrict__ s0, const float* __restrict__ s1,
               const float* __restrict__ s2,
               __half* __restrict__ d0, __half* __restrict__ d1, __half* __restrict__ d2)
{
    __shared__ float t[32][33];
    const float* in  = blockIdx.z == 0 ? s0 : (blockIdx.z == 1 ? s1 : s2);
    __half* out      = blockIdx.z == 0 ? d0 : (blockIdx.z == 1 ? d1 : d2);
    const int c0 = blockIdx.x * 32, r0 = blockIdx.y * 32;
    const int tx = threadIdx.x, ty = threadIdx.y;
#pragma unroll
    for (int i = ty; i < 32; i += 8)
        t[i][tx] = in[(long)(r0 + i) * CH + c0 + tx];
    __syncthreads();
#pragma unroll
    for (int i = ty; i < 32; i += 8)
        out[(long)(c0 + i) * CH + r0 + tx] = __float2half(t[tx][i]);
}

// ---------------- LayerNorm apply: f16 ctx + (mu, rstd) -> f16 out ----------------
__global__ __launch_bounds__(256)
void lnapply_k(const __half* __restrict__ ctx16, const float* __restrict__ musig,
               __half* __restrict__ out,
               const float* __restrict__ gamma, const float* __restrict__ beta)
{
    const long row = blockIdx.x;
    const int tid = threadIdx.x;
    const float mu   = musig[row * 2 + 0];
    const float rstd = musig[row * 2 + 1];
    const int c = tid * 4;

    const __half2* p = (const __half2*)(ctx16 + row * CH + c);
    float2 x0 = __half22float2(p[0]);
    float2 x1 = __half22float2(p[1]);
    float4 g  = *(const float4*)(gamma + c);
    float4 be = *(const float4*)(beta + c);

    __half2* o2 = (__half2*)(out + row * CH + c);
    o2[0] = __floats2half2_rn((x0.x - mu) * rstd * g.x + be.x,
                              (x0.y - mu) * rstd * g.y + be.y);
    o2[1] = __floats2half2_rn((x1.x - mu) * rstd * g.z + be.z,
                              (x1.y - mu) * rstd * g.w + be.w);
}

// ---------------- launch ----------------
extern "C" void kernel_launch(void* const* d_in, const int* in_sizes, int n_in,
                              void* d_out, int out_size)
{
    const float* Q     = (const float*)d_in[0];
    const float* Kk    = (const float*)d_in[1];
    const float* kmask = (const float*)d_in[2];
    const float* qmask = (const float*)d_in[3];
    const float* u     = (const float*)d_in[4];
    const float* dd    = (const float*)d_in[5];
    const float* W1    = (const float*)d_in[6];
    const float* b1    = (const float*)d_in[7];
    const float* W2    = (const float*)d_in[8];
    const float* b2    = (const float*)d_in[9];
    const float* gamma = (const float*)d_in[10];
    const float* beta  = (const float*)d_in[11];

    __half *hQ, *hK, *hKT, *hUT, *hW1T, *hW2T, *f1h, *f2h, *hS, *hLN, *hH;
    float  *part, *invs, *musig;
    cudaGetSymbolAddress((void**)&hQ,  g_hQ);
    cudaGetSymbolAddress((void**)&hK,  g_hK);
    cudaGetSymbolAddress((void**)&hKT, g_hKT);
    cudaGetSymbolAddress((void**)&hUT, g_hUT);
    cudaGetSymbolAddress((void**)&hW1T, g_hW1T);
    cudaGetSymbolAddress((void**)&hW2T, g_hW2T);
    cudaGetSymbolAddress((void**)&f1h, g_f1h);
    cudaGetSymbolAddress((void**)&f2h, g_f2h);
    cudaGetSymbolAddress((void**)&hS,  g_hS);
    cudaGetSymbolAddress((void**)&hLN, g_hLN);
    cudaGetSymbolAddress((void**)&hH,  g_hH);
    cudaGetSymbolAddress((void**)&part, g_part);
    cudaGetSymbolAddress((void**)&invs, g_invs);
    cudaGetSymbolAddress((void**)&musig, g_musig);

    const long TC  = (long)TT * CH;
    const long TTl = (long)TT * TT;

    float* out2 = (float*)d_out;
    float* outq = (float*)d_out;
    if ((long)out_size >= 2 * (long)NTC) out2 = (float*)d_out + NTC;

    cudaFuncSetAttribute(gemmv7<EPI_PROJ, true>,      cudaFuncAttributeMaxDynamicSharedMemorySize, SMEM_G);
    cudaFuncSetAttribute(gemmv7<EPI_EXP, true>,       cudaFuncAttributeMaxDynamicSharedMemorySize, SMEM_G);
    cudaFuncSetAttribute(gemmv7<EPI_CTX, true>,       cudaFuncAttributeMaxDynamicSharedMemorySize, SMEM_G);
    cudaFuncSetAttribute(gemmv7<EPI_BIAS_RELU, true>, cudaFuncAttributeMaxDynamicSharedMemorySize, SMEM_G);
    cudaFuncSetAttribute(gemmv7<EPI_BIAS, false>,     cudaFuncAttributeMaxDynamicSharedMemorySize, SMEM_G);

    // ---- conversions ----
    convq_k<<<NTC / 1024, 256>>>(Q, hQ, outq);                                        // 1
    convkt_k<<<dim3(CH / 32, TT / 32, BB), dim3(32, 8)>>>(Kk, hK, hKT, TT, CH, TC, TC); // 2
    transp3_k<<<dim3(CH / 32, CH / 32, 3), dim3(32, 8)>>>(u, W1, W2, hUT, hW1T, hW2T);  // 3

    // ---- 1+2) f1 = relu(Q@u)*d ; f2 = relu(K@u)  (merged, grid.z=2) ----
    gemmv7<EPI_PROJ, true><<<dim3(CH / BN, BB * TT / BM, 2), NTHR, SMEM_G>>>(
        hQ, hK, hUT, f1h, f2h, BB * TT, CH, CH, 0, 0, 0, dd, 0, nullptr, 0, 0.f, nullptr);

    // ---- 3) expS = exp((f1 @ f2^T)/32) masked -> f16, + row partial sums ----
    gemmv7<EPI_EXP, true><<<dim3(TT / BN, TT / BM, BB), NTHR, SMEM_G>>>(
        f1h, nullptr, f2h, hS, nullptr, TT, TT, CH, TC, TC, TTl, kmask, TT, nullptr, 0,
        1.0f / 32.0f, part);

    // ---- 4) invs = qmask / rowsum ----
    invs_k<<<BB * TT / 256, 256>>>(part, qmask, invs);

    // ---- 5) ctx16 = (expS @ K) * invs[row] + Q  (f16 out, + LN partial stats) ----
    //        f1h is dead (consumed by score GEMM) -> reuse as ctx16
    gemmv7<EPI_CTX, true><<<dim3(CH / BN, TT / BM, BB), NTHR, SMEM_G>>>(
        hS, nullptr, hKT, f1h, nullptr, TT, CH, TT, TTl, TC, TC, invs, TT, Q, TC, 0.f, part);

    // ---- 6) per-row (mu, rstd) ----
    musig_k<<<BB * TT / 256, 256>>>(part, musig);

    // ---- 7) LN apply: f16 in -> f16 out ----
    lnapply_k<<<BB * TT, 256>>>(f1h, musig, hLN, gamma, beta);

    // ---- 8) h = relu(LN @ W1 + b1) -> f16 ----
    gemmv7<EPI_BIAS_RELU, true><<<dim3(CH / BN, BB * TT / BM, 1), NTHR, SMEM_G>>>(
        hLN, nullptr, hW1T, hH, nullptr, BB * TT, CH, CH, 0, 0, 0, b1, 0, nullptr, 0, 0.f, nullptr);

    // ---- 9) out2 = h @ W2 + b2 (fp32 out) ----
    gemmv7<EPI_BIAS, false><<<dim3(CH / BN, BB * TT / BM, 1), NTHR, SMEM_G>>>(
        hH, nullptr, hW2T, out2, nullptr, BB * TT, CH, CH, 0, 0, 0, b2, 0, nullptr, 0, 0.f, nullptr);
}

// round 17
// speedup vs baseline: 1.0797x; 1.0108x over previous
#include <cuda_runtime.h>
#include <cuda_fp16.h>
#include <math.h>
#include <stdint.h>

#define BB  8
#define TT  2048
#define CH  1024

#define NTC   (BB * TT * CH)              // 16,777,216
#define NTT   ((size_t)BB * TT * TT)      // 33,554,432

// ---------------- scratch (no allocations allowed) ----------------
__device__ __half g_hQ [NTC];
__device__ __half g_hK [NTC];
__device__ __half g_hKT[NTC];             // per-batch [CH][TT]
__device__ __half g_hUT [CH * CH];
__device__ __half g_hW1T[CH * CH];
__device__ __half g_hW2T[CH * CH];
__device__ __half g_f1h[NTC];             // proj f1; later reused as f16 ctx
__device__ __half g_f2h[NTC];
__device__ __half g_hS [NTT];             // f16 exp(scores)
__device__ float  g_part[BB * TT * 16];
__device__ float  g_invs[BB * TT];
__device__ __half g_hLN[NTC];
__device__ __half g_hH [NTC];

enum { EPI_PROJ = 0, EPI_EXP, EPI_CTX, EPI_BIAS_RELU, EPI_BIAS };

// ---------------- PTX helpers ----------------
__device__ __forceinline__ uint32_t smem_u32(const void* p) {
    uint32_t a;
    asm("{ .reg .u64 t; cvta.to.shared.u64 t, %1; cvt.u32.u64 %0, t; }" : "=r"(a) : "l"(p));
    return a;
}
__device__ __forceinline__ void ldsm4(uint32_t* r, uint32_t addr) {
    asm volatile("ldmatrix.sync.aligned.m8n8.x4.shared.b16 {%0,%1,%2,%3}, [%4];"
        : "=r"(r[0]), "=r"(r[1]), "=r"(r[2]), "=r"(r[3]) : "r"(addr));
}
__device__ __forceinline__ void mma_f16(float* d, const uint32_t* a, const uint32_t* b) {
    asm volatile(
        "mma.sync.aligned.m16n8k16.row.col.f32.f16.f16.f32 "
        "{%0,%1,%2,%3}, {%4,%5,%6,%7}, {%8,%9}, {%0,%1,%2,%3};"
        : "+f"(d[0]), "+f"(d[1]), "+f"(d[2]), "+f"(d[3])
        : "r"(a[0]), "r"(a[1]), "r"(a[2]), "r"(a[3]), "r"(b[0]), "r"(b[1]));
}
#define CP16(dst, src) \
    asm volatile("cp.async.cg.shared.global [%0], [%1], 16;" :: "r"(dst), "l"(src) : "memory")
#define CP_COMMIT()  asm volatile("cp.async.commit_group;" ::: "memory")
#define CP_WAIT1()   asm volatile("cp.async.wait_group 1;" ::: "memory")
#define CP_WAIT0()   asm volatile("cp.async.wait_group 0;" ::: "memory")

// swizzled offset within a k32 subtile: rows of 64B (32 halves), 16B column c (0..3)
__device__ __forceinline__ uint32_t swz(int row, int c) {
    return (uint32_t)(row * 64 + (((c) ^ ((row >> 1) & 3)) << 4));
}

// CTA tile 128x128, STAGE = K64 (two k32 subtiles), 3-stage cp.async ring,
// 8 warps (4m x 2n) of 32x64, 256 threads, 2 CTAs/SM.
#define BM 128
#define BN 128
#define A_BYTES (BM * 64)                 // 8192 per subtile
#define B_BYTES (BN * 64)                 // 8192 per subtile
#define SUBSTG  (A_BYTES + B_BYTES)       // 16384
#define STAGE   (2 * SUBSTG)              // 32768 (K=64)
#define SMEM_G  (3 * STAGE)               // 98304
#define NTHR    256

#define GEMM_SETUP()                                                           \
    extern __shared__ char smem[];                                             \
    const uint32_t sb = smem_u32(smem);                                        \
    const int tid = threadIdx.x, lane = tid & 31, warp = tid >> 5;             \
    const int wm = warp >> 1, wn = warp & 1;                                   \
    const int z = blockIdx.z;                                                  \
    uint32_t adst[2], bdst[2];                                                 \
    const __half* asrc[2];                                                     \
    const __half* bsrc[2];                                                     \
    _Pragma("unroll")                                                          \
    for (int i = 0; i < 2; i++) {                                              \
        int q = tid + i * NTHR, r = q >> 2, c = q & 3;                         \
        adst[i] = swz(r, c);                                                   \
        asrc[i] = Ap + (long)r * K + c * 8;                                    \
        bdst[i] = A_BYTES + swz(r, c);                                         \
        bsrc[i] = Bp + (long)r * K + c * 8;                                    \
    }                                                                          \
    const int q8 = lane >> 3, rr = lane & 7;                                   \
    const int rA = wm * 32 + (q8 & 1) * 8 + rr;                                \
    const int xA = (rA >> 1) & 3;                                              \
    const int cA = q8 >> 1;                                                    \
    const int rB = wn * 64 + (q8 >> 1) * 8 + rr;                               \
    const int xB = (rB >> 1) & 3;                                              \
    const int cB = q8 & 1;

// one stage = K64: two k32 subtiles, single commit
#define ISSUE(st)                                                              \
    do {                                                                       \
        const uint32_t _s = sb + ((st) % 3) * STAGE;                           \
        _Pragma("unroll")                                                      \
        for (int _sub = 0; _sub < 2; _sub++) {                                 \
            const long _ko = (long)(st) * 64 + _sub * 32;                      \
            const uint32_t _d = _s + _sub * SUBSTG;                            \
            CP16(_d + adst[0], asrc[0] + _ko);                                 \
            CP16(_d + adst[1], asrc[1] + _ko);                                 \
            CP16(_d + bdst[0], bsrc[0] + _ko);                                 \
            CP16(_d + bdst[1], bsrc[1] + _ko);                                 \
        }                                                                      \
        CP_COMMIT();                                                           \
    } while (0)

#define MAINLOOP()                                                             \
    ISSUE(0);                                                                  \
    ISSUE(1);                                                                  \
    const int nSt = K / 64;                                                    \
    for (int st = 0; st < nSt; st++) {                                         \
        if (st + 1 < nSt) CP_WAIT1(); else CP_WAIT0();                         \
        __syncthreads();                                                       \
        const uint32_t stbase = sb + (st % 3) * STAGE;                         \
        _Pragma("unroll")                                                      \
        for (int sub = 0; sub < 2; sub++) {                                    \
            const uint32_t sbase = stbase + sub * SUBSTG;                      \
            _Pragma("unroll")                                                  \
            for (int s = 0; s < 2; s++) {                                      \
                uint32_t af[2][4];                                             \
                _Pragma("unroll")                                              \
                for (int mi = 0; mi < 2; mi++)                                 \
                    ldsm4(af[mi], sbase + (uint32_t)((rA + mi * 16) * 64) +    \
                                  (uint32_t)((((2 * s + cA) ^ xA)) << 4));     \
                _Pragma("unroll")                                              \
                for (int nip = 0; nip < 4; nip++) {                            \
                    uint32_t t4[4];                                            \
                    ldsm4(t4, sbase + A_BYTES + (uint32_t)((rB + nip * 16) * 64) + \
                              (uint32_t)((((2 * s + cB) ^ xB)) << 4));         \
                    _Pragma("unroll")                                          \
                    for (int mi = 0; mi < 2; mi++) mma_f16(acc[mi][2 * nip],     af[mi], &t4[0]); \
                    _Pragma("unroll")                                          \
                    for (int mi = 0; mi < 2; mi++) mma_f16(acc[mi][2 * nip + 1], af[mi], &t4[2]); \
                }                                                              \
            }                                                                  \
        }                                                                      \
        if (st + 2 < nSt) ISSUE(st + 2);                                       \
    }

// ---------------- f16-in / f32-acc GEMM, fused epilogues ----------------
template <int EPI, bool OUTH>
__global__ void __launch_bounds__(NTHR, 2)
gemmv7(const __half* __restrict__ A, const __half* __restrict__ A2,
       const __half* __restrict__ B, void* __restrict__ Cv, void* __restrict__ Cv2,
       int M, int N, int K, long sA, long sB, long sC,
       const float* __restrict__ vec, long sVec,
       const float* __restrict__ add, long sAdd, float scale,
       float* __restrict__ part)
{
    const __half* Abase = A;
    void* Cbase = Cv;
    if (EPI == EPI_PROJ && blockIdx.z == 1) { Abase = A2; Cbase = Cv2; }
    const __half* Ap = Abase + (long)blockIdx.z * sA + (long)(blockIdx.y * BM) * K;
    const __half* Bp = B + (long)blockIdx.z * sB + (long)(blockIdx.x * BN) * K;

    GEMM_SETUP();

    float acc[2][8][4];
#pragma unroll
    for (int mi = 0; mi < 2; mi++)
#pragma unroll
        for (int ni = 0; ni < 8; ni++)
#pragma unroll
            for (int e = 0; e < 4; e++) acc[mi][ni][e] = 0.f;

    MAINLOOP();

    const float* vv = vec ? vec + (long)z * sVec : nullptr;
    const long cBase = (long)z * sC;

    if (EPI == EPI_EXP) {
        float rsl[2][2] = {{0.f, 0.f}, {0.f, 0.f}};
#pragma unroll
        for (int mi = 0; mi < 2; mi++) {
            const int r0 = blockIdx.y * BM + wm * 32 + mi * 16 + (lane >> 2);
#pragma unroll
            for (int ni = 0; ni < 8; ni++) {
                const int c = blockIdx.x * BN + wn * 64 + ni * 8 + (lane & 3) * 2;
                const float m0 = vv[c], m1 = vv[c + 1];
#pragma unroll
                for (int p = 0; p < 2; p++) {
                    const int r = r0 + p * 8;
                    float e0 = (m0 == 0.f) ? 0.f : __expf(acc[mi][ni][p * 2 + 0] * scale);
                    float e1 = (m1 == 0.f) ? 0.f : __expf(acc[mi][ni][p * 2 + 1] * scale);
                    __half2 h = __floats2half2_rn(e0, e1);
                    *(__half2*)((__half*)Cv + cBase + (long)r * N + c) = h;
                    float2 fr = __half22float2(h);
                    rsl[mi][p] += fr.x + fr.y;
                }
            }
        }
        float* rsf = (float*)(smem + (nSt % 3) * STAGE);
#pragma unroll
        for (int mi = 0; mi < 2; mi++)
#pragma unroll
            for (int p = 0; p < 2; p++) {
                float s = rsl[mi][p];
                s += __shfl_xor_sync(0xffffffffu, s, 1);
                s += __shfl_xor_sync(0xffffffffu, s, 2);
                if ((lane & 3) == 0)
                    rsf[(wm * 32 + mi * 16 + p * 8 + (lane >> 2)) * 2 + wn] = s;
            }
        __syncthreads();
        if (tid < BM) {
            float s = rsf[tid * 2] + rsf[tid * 2 + 1];
            part[((long)z * TT + blockIdx.y * BM + tid) * 16 + blockIdx.x] = s;
        }
        return;
    }

    if (EPI == EPI_CTX) {
        // ctx = acc*invs[row] + Q(f16)  -> f16; accumulate per-row sum & sumsq
        // of the f16-rounded values (self-consistent with LN apply).
        const __half* adb = (const __half*)add + (long)z * sAdd;
        float s1l[2][2] = {{0.f, 0.f}, {0.f, 0.f}};
        float s2l[2][2] = {{0.f, 0.f}, {0.f, 0.f}};
#pragma unroll
        for (int mi = 0; mi < 2; mi++) {
            const int r0 = blockIdx.y * BM + wm * 32 + mi * 16 + (lane >> 2);
            const float rowS[2] = { vv[r0], vv[r0 + 8] };
#pragma unroll
            for (int ni = 0; ni < 8; ni++) {
                const int c = blockIdx.x * BN + wn * 64 + ni * 8 + (lane & 3) * 2;
#pragma unroll
                for (int p = 0; p < 2; p++) {
                    const int r = r0 + p * 8;
                    float2 a2 = __half22float2(*(const __half2*)(adb + (long)r * N + c));
                    float v0 = acc[mi][ni][p * 2 + 0] * rowS[p] + a2.x;
                    float v1 = acc[mi][ni][p * 2 + 1] * rowS[p] + a2.y;
                    __half2 h = __floats2half2_rn(v0, v1);
                    *(__half2*)((__half*)Cv + cBase + (long)r * N + c) = h;
                    float2 fr = __half22float2(h);
                    s1l[mi][p] += fr.x + fr.y;
                    s2l[mi][p] += fr.x * fr.x + fr.y * fr.y;
                }
            }
        }
        float* rsf = (float*)(smem + (nSt % 3) * STAGE);
        float* rsq = rsf + 256;
#pragma unroll
        for (int mi = 0; mi < 2; mi++)
#pragma unroll
            for (int p = 0; p < 2; p++) {
                float s = s1l[mi][p], q = s2l[mi][p];
                s += __shfl_xor_sync(0xffffffffu, s, 1);
                s += __shfl_xor_sync(0xffffffffu, s, 2);
                q += __shfl_xor_sync(0xffffffffu, q, 1);
                q += __shfl_xor_sync(0xffffffffu, q, 2);
                if ((lane & 3) == 0) {
                    const int rl = wm * 32 + mi * 16 + p * 8 + (lane >> 2);
                    rsf[rl * 2 + wn] = s;
                    rsq[rl * 2 + wn] = q;
                }
            }
        __syncthreads();
        if (tid < BM) {
            const long prow = ((long)z * TT + blockIdx.y * BM + tid) * 16 + blockIdx.x * 2;
            part[prow + 0] = rsf[tid * 2] + rsf[tid * 2 + 1];
            part[prow + 1] = rsq[tid * 2] + rsq[tid * 2 + 1];
        }
        return;
    }

    const float* adb = add ? add + (long)z * sAdd : nullptr;
    (void)adb;

#pragma unroll
    for (int mi = 0; mi < 2; mi++) {
        const int r0 = blockIdx.y * BM + wm * 32 + mi * 16 + (lane >> 2);
#pragma unroll
        for (int ni = 0; ni < 8; ni++) {
            const int c = blockIdx.x * BN + wn * 64 + ni * 8 + (lane & 3) * 2;
#pragma unroll
            for (int p = 0; p < 2; p++) {
                const int r = r0 + p * 8;
                float v0 = acc[mi][ni][p * 2 + 0];
                float v1 = acc[mi][ni][p * 2 + 1];
                if (EPI == EPI_PROJ) {
                    v0 = fmaxf(v0, 0.f); v1 = fmaxf(v1, 0.f);
                    if (z == 0) { v0 *= vv[c]; v1 *= vv[c + 1]; }
                }
                if (EPI == EPI_BIAS_RELU) { v0 = fmaxf(v0 + vv[c], 0.f); v1 = fmaxf(v1 + vv[c + 1], 0.f); }
                if (EPI == EPI_BIAS)      { v0 += vv[c]; v1 += vv[c + 1]; }
                if (OUTH) {
                    __half* op = (__half*)Cbase + cBase + (long)r * N + c;
                    *(__half2*)op = __floats2half2_rn(v0, v1);
                } else {
                    float* op = (float*)Cbase + cBase + (long)r * N + c;
                    *(float2*)op = make_float2(v0, v1);
                }
            }
        }
    }
}

// ---------------- invs: qmask/rowsum ----------------
__global__ __launch_bounds__(256)
void invs_k(const float* __restrict__ part, const float* __restrict__ qmask,
            float* __restrict__ invs)
{
    const int i = blockIdx.x * 256 + threadIdx.x;
    float s = 0.f;
#pragma unroll
    for (int j = 0; j < 16; j++) s += part[(long)i * 16 + j];
    invs[i] = qmask[i] / s;
}

// ---------------- Q convert: f32 -> f16, plus fp32 copy to output ----------------
__global__ __launch_bounds__(256)
void convq_k(const float* __restrict__ in, __half* __restrict__ out, float* __restrict__ outc)
{
    const int i = blockIdx.x * 256 + threadIdx.x;
    float4 v = ((const float4*)in)[i];
    __half2* o = (__half2*)out + (long)i * 2;
    o[0] = __floats2half2_rn(v.x, v.y);
    o[1] = __floats2half2_rn(v.z, v.w);
    ((float4*)outc)[i] = v;
}

// ---------------- K convert + transpose (64x32 tile, 128B transposed writes) ----
__global__ __launch_bounds__(256)
void convkt_k(const float* __restrict__ in, __half* __restrict__ lin, __half* __restrict__ tr,
              int R, int C, long sIn, long sOut)
{
    __shared__ float t[64][33];
    const long zi = (long)blockIdx.z * sIn, zo = (long)blockIdx.z * sOut;
    const int c0 = blockIdx.x * 32, r0 = blockIdx.y * 64;
    const int tx = threadIdx.x, ty = threadIdx.y;
    // load 64 rows x 32 cols (coalesced 128B), emit f16 linear copy (64B/warp)
#pragma unroll
    for (int j = 0; j < 8; j++) {
        const int row = j * 8 + ty;
        float v = in[zi + (long)(r0 + row) * C + c0 + tx];
        t[row][tx] = v;
        lin[zi + (long)(r0 + row) * C + c0 + tx] = __float2half(v);
    }
    __syncthreads();
    // write 32 output rows (c-dim), each 64 long (r-dim): warp writes 32 x half2 = 128B
#pragma unroll
    for (int j = 0; j < 4; j++) {
        const int i = j * 8 + ty;          // output row c0+i
        __half2 h = __floats2half2_rn(t[2 * tx][i], t[2 * tx + 1][i]);
        *(__half2*)(tr + zo + (long)(c0 + i) * R + r0 + 2 * tx) = h;
    }
}

// ---------------- batched square transpose f32 -> f16: three matrices ----------------
__global__ __launch_bounds__(256)
void transp3_k(const float* __restrict__ s0, const float* __restrict__ s1,
               const float* __restrict__ s2,
               __half* __restrict__ d0, __half* __restrict__ d1, __half* __restrict__ d2)
{
    __shared__ float t[32][33];
    const float* in  = blockIdx.z == 0 ? s0 : (blockIdx.z == 1 ? s1 : s2);
    __half* out      = blockIdx.z == 0 ? d0 : (blockIdx.z == 1 ? d1 : d2);
    const int c0 = blockIdx.x * 32, r0 = blockIdx.y * 32;
    const int tx = threadIdx.x, ty = threadIdx.y;
#pragma unroll
    for (int i = ty; i < 32; i += 8)
        t[i][tx] = in[(long)(r0 + i) * CH + c0 + tx];
    __syncthreads();
#pragma unroll
    for (int i = ty; i < 32; i += 8)
        out[(long)(c0 + i) * CH + r0 + tx] = __float2half(t[tx][i]);
}

// ---------------- LayerNorm apply (stats from partials): f16 ctx -> f16 out -----
__global__ __launch_bounds__(256)
void lnapply_k(const __half* __restrict__ ctx16, const float* __restrict__ part,
               __half* __restrict__ out,
               const float* __restrict__ gamma, const float* __restrict__ beta)
{
    const long row = blockIdx.x;
    const int tid = threadIdx.x;
    float s = 0.f, q = 0.f;
#pragma unroll
    for (int j = 0; j < 8; j++) {
        s += part[row * 16 + j * 2 + 0];
        q += part[row * 16 + j * 2 + 1];
    }
    const float mu   = s * (1.f / CH);
    const float rstd = rsqrtf(q * (1.f / CH) - mu * mu + 1e-6f);
    const int c = tid * 4;

    const __half2* p = (const __half2*)(ctx16 + row * CH + c);
    float2 x0 = __half22float2(p[0]);
    float2 x1 = __half22float2(p[1]);
    float4 g  = *(const float4*)(gamma + c);
    float4 be = *(const float4*)(beta + c);

    __half2* o2 = (__half2*)(out + row * CH + c);
    o2[0] = __floats2half2_rn((x0.x - mu) * rstd * g.x + be.x,
                              (x0.y - mu) * rstd * g.y + be.y);
    o2[1] = __floats2half2_rn((x1.x - mu) * rstd * g.z + be.z,
                              (x1.y - mu) * rstd * g.w + be.w);
}

// ---------------- launch ----------------
extern "C" void kernel_launch(void* const* d_in, const int* in_sizes, int n_in,
                              void* d_out, int out_size)
{
    const float* Q     = (const float*)d_in[0];
    const float* Kk    = (const float*)d_in[1];
    const float* kmask = (const float*)d_in[2];
    const float* qmask = (const float*)d_in[3];
    const float* u     = (const float*)d_in[4];
    const float* dd    = (const float*)d_in[5];
    const float* W1    = (const float*)d_in[6];
    const float* b1    = (const float*)d_in[7];
    const float* W2    = (const float*)d_in[8];
    const float* b2    = (const float*)d_in[9];
    const float* gamma = (const float*)d_in[10];
    const float* beta  = (const float*)d_in[11];

    __half *hQ, *hK, *hKT, *hUT, *hW1T, *hW2T, *f1h, *f2h, *hS, *hLN, *hH;
    float  *part, *invs;
    cudaGetSymbolAddress((void**)&hQ,  g_hQ);
    cudaGetSymbolAddress((void**)&hK,  g_hK);
    cudaGetSymbolAddress((void**)&hKT, g_hKT);
    cudaGetSymbolAddress((void**)&hUT, g_hUT);
    cudaGetSymbolAddress((void**)&hW1T, g_hW1T);
    cudaGetSymbolAddress((void**)&hW2T, g_hW2T);
    cudaGetSymbolAddress((void**)&f1h, g_f1h);
    cudaGetSymbolAddress((void**)&f2h, g_f2h);
    cudaGetSymbolAddress((void**)&hS,  g_hS);
    cudaGetSymbolAddress((void**)&hLN, g_hLN);
    cudaGetSymbolAddress((void**)&hH,  g_hH);
    cudaGetSymbolAddress((void**)&part, g_part);
    cudaGetSymbolAddress((void**)&invs, g_invs);

    const long TC  = (long)TT * CH;
    const long TTl = (long)TT * TT;

    float* out2 = (float*)d_out;
    float* outq = (float*)d_out;
    if ((long)out_size >= 2 * (long)NTC) out2 = (float*)d_out + NTC;

    cudaFuncSetAttribute(gemmv7<EPI_PROJ, true>,      cudaFuncAttributeMaxDynamicSharedMemorySize, SMEM_G);
    cudaFuncSetAttribute(gemmv7<EPI_EXP, true>,       cudaFuncAttributeMaxDynamicSharedMemorySize, SMEM_G);
    cudaFuncSetAttribute(gemmv7<EPI_CTX, true>,       cudaFuncAttributeMaxDynamicSharedMemorySize, SMEM_G);
    cudaFuncSetAttribute(gemmv7<EPI_BIAS_RELU, true>, cudaFuncAttributeMaxDynamicSharedMemorySize, SMEM_G);
    cudaFuncSetAttribute(gemmv7<EPI_BIAS, false>,     cudaFuncAttributeMaxDynamicSharedMemorySize, SMEM_G);

    // ---- conversions ----
    convq_k<<<NTC / 1024, 256>>>(Q, hQ, outq);                                        // 1
    convkt_k<<<dim3(CH / 32, TT / 64, BB), dim3(32, 8)>>>(Kk, hK, hKT, TT, CH, TC, TC); // 2
    transp3_k<<<dim3(CH / 32, CH / 32, 3), dim3(32, 8)>>>(u, W1, W2, hUT, hW1T, hW2T);  // 3

    // ---- 1+2) f1 = relu(Q@u)*d ; f2 = relu(K@u)  (merged, grid.z=2) ----
    gemmv7<EPI_PROJ, true><<<dim3(CH / BN, BB * TT / BM, 2), NTHR, SMEM_G>>>(
        hQ, hK, hUT, f1h, f2h, BB * TT, CH, CH, 0, 0, 0, dd, 0, nullptr, 0, 0.f, nullptr);

    // ---- 3) expS = exp((f1 @ f2^T)/32) masked -> f16, + row partial sums ----
    gemmv7<EPI_EXP, true><<<dim3(TT / BN, TT / BM, BB), NTHR, SMEM_G>>>(
        f1h, nullptr, f2h, hS, nullptr, TT, TT, CH, TC, TC, TTl, kmask, TT, nullptr, 0,
        1.0f / 32.0f, part);

    // ---- 4) invs = qmask / rowsum ----
    invs_k<<<BB * TT / 256, 256>>>(part, qmask, invs);

    // ---- 5) ctx16 = (expS @ K) * invs[row] + Q(f16)  (f16 out, + LN stats) ----
    //        f1h is dead (consumed by score GEMM) -> reuse as ctx16
    gemmv7<EPI_CTX, true><<<dim3(CH / BN, TT / BM, BB), NTHR, SMEM_G>>>(
        hS, nullptr, hKT, f1h, nullptr, TT, CH, TT, TTl, TC, TC, invs, TT,
        (const float*)hQ, TC, 0.f, part);

    // ---- 6) LN apply (stats reduced in-kernel): f16 in -> f16 out ----
    lnapply_k<<<BB * TT, 256>>>(f1h, part, hLN, gamma, beta);

    // ---- 7) h = relu(LN @ W1 + b1) -> f16 ----
    gemmv7<EPI_BIAS_RELU, true><<<dim3(CH / BN, BB * TT / BM, 1), NTHR, SMEM_G>>>(
        hLN, nullptr, hW1T, hH, nullptr, BB * TT, CH, CH, 0, 0, 0, b1, 0, nullptr, 0, 0.f, nullptr);

    // ---- 8) out2 = h @ W2 + b2 (fp32 out) ----
    gemmv7<EPI_BIAS, false><<<dim3(CH / BN, BB * TT / BM, 1), NTHR, SMEM_G>>>(
        hH, nullptr, hW2T, out2, nullptr, BB * TT, CH, CH, 0, 0, 0, b2, 0, nullptr, 0, 0.f, nullptr);
}